// round 10
// baseline (speedup 1.0000x reference)
#include <cuda_runtime.h>
#include <cstdint>

#define BATCH   2
#define S_LEN   2048
#define DIM     2048
#define NHEADS  16
#define KVHEADS 8
#define HD      128

constexpr int BM = 128, BN = 128, BK = 8;

// ---------------- static scratch ----------------
__device__ float g_Q [(size_t)BATCH * S_LEN * NHEADS  * HD];
__device__ float g_K [(size_t)BATCH * S_LEN * KVHEADS * HD];
__device__ float g_V [(size_t)BATCH * S_LEN * KVHEADS * HD];
__device__ float g_AO[(size_t)BATCH * S_LEN * NHEADS  * HD];

// ---------------- classic SIMT fp32 GEMM (row-major C=A@B) ----------------
__global__ __launch_bounds__(256)
void sgemm(const float* __restrict__ A, const float* __restrict__ B,
           float* __restrict__ C, int K, int lda, int ldb, int ldc)
{
    const int bm = blockIdx.y, bn = blockIdx.x;

    __shared__ float As[BK][BM + 4];
    __shared__ float Bs[BK][BN];

    const int tid = threadIdx.x;
    const int tx = tid & 15;
    const int ty = tid >> 4;

    const int arow = tid >> 1;
    const int acol = (tid & 1) << 2;
    const int brow = tid >> 5;
    const int bcol = (tid & 31) << 2;

    float acc[8][8];
    #pragma unroll
    for (int i = 0; i < 8; i++)
        #pragma unroll
        for (int j = 0; j < 8; j++) acc[i][j] = 0.0f;

    const int ktiles = K / BK;
    const float* Ag = A + (size_t)(bm * BM + arow) * lda + acol;
    const float* Bg = B + (size_t)brow * ldb + bn * BN + bcol;

    for (int kt = 0; kt < ktiles; kt++) {
        float4 av = *reinterpret_cast<const float4*>(Ag + (size_t)kt * BK);
        As[acol + 0][arow] = av.x;
        As[acol + 1][arow] = av.y;
        As[acol + 2][arow] = av.z;
        As[acol + 3][arow] = av.w;
        *reinterpret_cast<float4*>(&Bs[brow][bcol]) =
            *reinterpret_cast<const float4*>(Bg + (size_t)kt * BK * ldb);
        __syncthreads();

        #pragma unroll
        for (int k = 0; k < BK; k++) {
            float ra[8], rb[8];
            *reinterpret_cast<float4*>(ra)     = *reinterpret_cast<const float4*>(&As[k][ty * 4]);
            *reinterpret_cast<float4*>(ra + 4) = *reinterpret_cast<const float4*>(&As[k][64 + ty * 4]);
            *reinterpret_cast<float4*>(rb)     = *reinterpret_cast<const float4*>(&Bs[k][tx * 4]);
            *reinterpret_cast<float4*>(rb + 4) = *reinterpret_cast<const float4*>(&Bs[k][64 + tx * 4]);
            #pragma unroll
            for (int i = 0; i < 8; i++)
                #pragma unroll
                for (int j = 0; j < 8; j++)
                    acc[i][j] += ra[i] * rb[j];
        }
        __syncthreads();
    }

    #pragma unroll
    for (int ih = 0; ih < 2; ih++)
        #pragma unroll
        for (int i = 0; i < 4; i++) {
            const size_t r = (size_t)(bm * BM + ih * 64 + ty * 4 + i);
            #pragma unroll
            for (int jh = 0; jh < 2; jh++) {
                float4 v;
                v.x = acc[ih * 4 + i][jh * 4 + 0];
                v.y = acc[ih * 4 + i][jh * 4 + 1];
                v.z = acc[ih * 4 + i][jh * 4 + 2];
                v.w = acc[ih * 4 + i][jh * 4 + 3];
                *reinterpret_cast<float4*>(C + r * ldc + bn * BN + jh * 64 + tx * 4) = v;
            }
        }
}

// ---------------- fused causal flash attention with inline half-split RoPE ----------------
#define QROWPAD 132
#define PROWPAD 68

__global__ __launch_bounds__(256)
void flash_attn(const float* __restrict__ Q, const float* __restrict__ K,
                const float* __restrict__ V, float* __restrict__ O)
{
    extern __shared__ float sm[];
    float* Qs   = sm;
    float* KVs  = Qs + 64 * QROWPAD;
    float* Ps   = KVs + 64 * QROWPAD;
    float* Mrow = Ps + 64 * PROWPAD;
    float* Lrow = Mrow + 64;
    float* Srow = Lrow + 64;
    float* Invf = Srow + 64;

    const int tid = threadIdx.x;
    const int tx = tid & 15, ty = tid >> 4;
    const int qr0 = blockIdx.x * 64;
    const int bh = blockIdx.y;
    const int b = bh >> 4, h = bh & 15;
    const int kvh = h >> 1;
    const float scale = 0.08838834764831845f;

    const float* Qbase = Q + ((size_t)(b * S_LEN + qr0) * NHEADS + h) * HD;
    #pragma unroll
    for (int i = 0; i < 8; i++) {
        int v = tid + i * 256;
        int r = v >> 5, c4 = (v & 31) << 2;
        *reinterpret_cast<float4*>(&Qs[r * QROWPAD + c4]) =
            *reinterpret_cast<const float4*>(Qbase + (size_t)r * (NHEADS * HD) + c4);
    }
    if (tid < 64) {
        Mrow[tid] = -INFINITY;
        Lrow[tid] = 0.0f;
        Invf[tid] = (float)exp2(-(double)tid * (13.287712379549449 / 64.0));
    }
    __syncthreads();

    // RoPE on Q tile — NOTE: sincosf(x, &sin, &cos)
    #pragma unroll
    for (int pp = 0; pp < 16; pp++) {
        int p = tid + pp * 256;
        int r = p >> 6, d = p & 63;
        float ang = (float)(qr0 + r) * Invf[d];
        float c, sn; sincosf(ang, &sn, &c);
        float a  = Qs[r * QROWPAD + d];
        float bb = Qs[r * QROWPAD + d + 64];
        Qs[r * QROWPAD + d]      = a  * c - bb * sn;
        Qs[r * QROWPAD + d + 64] = bb * c + a  * sn;
    }

    float acc[4][8];
    #pragma unroll
    for (int i = 0; i < 4; i++)
        #pragma unroll
        for (int j = 0; j < 8; j++) acc[i][j] = 0.0f;

    const float* Kbase = K + ((size_t)b * S_LEN * KVHEADS + kvh) * HD;
    const float* Vbase = V + ((size_t)b * S_LEN * KVHEADS + kvh) * HD;

    for (int j0 = 0; j0 <= qr0; j0 += 64) {
        __syncthreads();
        #pragma unroll
        for (int i = 0; i < 8; i++) {
            int v = tid + i * 256;
            int r = v >> 5, c4 = (v & 31) << 2;
            *reinterpret_cast<float4*>(&KVs[r * QROWPAD + c4]) =
                *reinterpret_cast<const float4*>(Kbase + (size_t)(j0 + r) * (KVHEADS * HD) + c4);
        }
        __syncthreads();

        // RoPE on K tile — sincosf(x, &sin, &cos)
        #pragma unroll
        for (int pp = 0; pp < 16; pp++) {
            int p = tid + pp * 256;
            int r = p >> 6, d = p & 63;
            float ang = (float)(j0 + r) * Invf[d];
            float c, sn; sincosf(ang, &sn, &c);
            float a  = KVs[r * QROWPAD + d];
            float bb = KVs[r * QROWPAD + d + 64];
            KVs[r * QROWPAD + d]      = a  * c - bb * sn;
            KVs[r * QROWPAD + d + 64] = bb * c + a  * sn;
        }
        __syncthreads();

        float s[4][4];
        #pragma unroll
        for (int i = 0; i < 4; i++)
            #pragma unroll
            for (int j = 0; j < 4; j++) s[i][j] = 0.0f;

        for (int d = 0; d < HD; d += 4) {
            float4 qa[4], kb[4];
            #pragma unroll
            for (int i = 0; i < 4; i++)
                qa[i] = *reinterpret_cast<const float4*>(&Qs[(ty * 4 + i) * QROWPAD + d]);
            #pragma unroll
            for (int j = 0; j < 4; j++)
                kb[j] = *reinterpret_cast<const float4*>(&KVs[(j * 16 + tx) * QROWPAD + d]);
            #pragma unroll
            for (int i = 0; i < 4; i++)
                #pragma unroll
                for (int j = 0; j < 4; j++)
                    s[i][j] += qa[i].x * kb[j].x + qa[i].y * kb[j].y
                             + qa[i].z * kb[j].z + qa[i].w * kb[j].w;
        }

        #pragma unroll
        for (int i = 0; i < 4; i++) {
            int rg = qr0 + ty * 4 + i;
            #pragma unroll
            for (int j = 0; j < 4; j++) {
                int cg = j0 + j * 16 + tx;
                float val = s[i][j] * scale;
                if (cg > rg) val = -INFINITY;
                Ps[(ty * 4 + i) * PROWPAD + j * 16 + tx] = val;
            }
        }
        __syncthreads();

        #pragma unroll
        for (int i = 0; i < 8; i++) {
            int v = tid + i * 256;
            int r = v >> 5, c4 = (v & 31) << 2;
            *reinterpret_cast<float4*>(&KVs[r * QROWPAD + c4]) =
                *reinterpret_cast<const float4*>(Vbase + (size_t)(j0 + r) * (KVHEADS * HD) + c4);
        }
        if (tid < 64) {
            float mold = Mrow[tid];
            float mt = mold;
            #pragma unroll 8
            for (int j = 0; j < 64; j++) mt = fmaxf(mt, Ps[tid * PROWPAD + j]);
            float factor = expf(mold - mt);
            float sum = 0.0f;
            #pragma unroll 8
            for (int j = 0; j < 64; j++) {
                float p = expf(Ps[tid * PROWPAD + j] - mt);
                Ps[tid * PROWPAD + j] = p;
                sum += p;
            }
            Mrow[tid] = mt;
            Lrow[tid] = Lrow[tid] * factor + sum;
            Srow[tid] = factor;
        }
        __syncthreads();

        #pragma unroll
        for (int i = 0; i < 4; i++) {
            float f = Srow[ty * 4 + i];
            #pragma unroll
            for (int j = 0; j < 8; j++) acc[i][j] *= f;
        }
        for (int j = 0; j < 64; j++) {
            float pr[4];
            #pragma unroll
            for (int i = 0; i < 4; i++) pr[i] = Ps[(ty * 4 + i) * PROWPAD + j];
            float4 v0 = *reinterpret_cast<const float4*>(&KVs[j * QROWPAD + tx * 8]);
            float4 v1 = *reinterpret_cast<const float4*>(&KVs[j * QROWPAD + tx * 8 + 4]);
            #pragma unroll
            for (int i = 0; i < 4; i++) {
                acc[i][0] += pr[i] * v0.x; acc[i][1] += pr[i] * v0.y;
                acc[i][2] += pr[i] * v0.z; acc[i][3] += pr[i] * v0.w;
                acc[i][4] += pr[i] * v1.x; acc[i][5] += pr[i] * v1.y;
                acc[i][6] += pr[i] * v1.z; acc[i][7] += pr[i] * v1.w;
            }
        }
    }

    float* Obase = O + ((size_t)(b * S_LEN + qr0) * NHEADS + h) * HD;
    #pragma unroll
    for (int i = 0; i < 4; i++) {
        int r = ty * 4 + i;
        float inv = 1.0f / Lrow[r];
        float4 o0, o1;
        o0.x = acc[i][0] * inv; o0.y = acc[i][1] * inv;
        o0.z = acc[i][2] * inv; o0.w = acc[i][3] * inv;
        o1.x = acc[i][4] * inv; o1.y = acc[i][5] * inv;
        o1.z = acc[i][6] * inv; o1.w = acc[i][7] * inv;
        *reinterpret_cast<float4*>(Obase + (size_t)r * (NHEADS * HD) + tx * 8)     = o0;
        *reinterpret_cast<float4*>(Obase + (size_t)r * (NHEADS * HD) + tx * 8 + 4) = o1;
    }
}

// ---------------- driver ----------------
extern "C" void kernel_launch(void* const* d_in, const int* in_sizes, int n_in,
                              void* d_out, int out_size)
{
    const float* x  = (const float*)d_in[0];
    const float* Wq = (const float*)d_in[1];
    const float* Wk = (const float*)d_in[2];
    const float* Wv = (const float*)d_in[3];
    const float* Wo = (const float*)d_in[4];
    float* out = (float*)d_out;

    float *Q, *K, *V, *AO;
    cudaGetSymbolAddress((void**)&Q,  g_Q);
    cudaGetSymbolAddress((void**)&K,  g_K);
    cudaGetSymbolAddress((void**)&V,  g_V);
    cudaGetSymbolAddress((void**)&AO, g_AO);

    const int M = BATCH * S_LEN;
    dim3 blk(256);

    sgemm<<<dim3((NHEADS * HD) / BN, M / BM), blk>>>(
        x, Wq, Q, DIM, DIM, NHEADS * HD, NHEADS * HD);
    sgemm<<<dim3((KVHEADS * HD) / BN, M / BM), blk>>>(
        x, Wk, K, DIM, DIM, KVHEADS * HD, KVHEADS * HD);
    sgemm<<<dim3((KVHEADS * HD) / BN, M / BM), blk>>>(
        x, Wv, V, DIM, DIM, KVHEADS * HD, KVHEADS * HD);

    {
        const int smem = (64 * QROWPAD * 2 + 64 * PROWPAD + 256) * (int)sizeof(float);
        cudaFuncSetAttribute(flash_attn, cudaFuncAttributeMaxDynamicSharedMemorySize, smem);
        flash_attn<<<dim3(S_LEN / 64, BATCH * NHEADS), blk, smem>>>(Q, K, V, AO);
    }

    sgemm<<<dim3(DIM / BN, M / BM), blk>>>(
        AO, Wo, out, NHEADS * HD, NHEADS * HD, DIM, DIM);
}

// round 11
// speedup vs baseline: 1.0494x; 1.0494x over previous
#include <cuda_runtime.h>
#include <mma.h>
#include <cstdint>

using namespace nvcuda;

#define BATCH   2
#define S_LEN   2048
#define DIM     2048
#define NHEADS  16
#define KVHEADS 8
#define HD      128

// ---------------- static scratch ----------------
__device__ float g_Q [(size_t)BATCH * S_LEN * NHEADS  * HD];
__device__ float g_K [(size_t)BATCH * S_LEN * KVHEADS * HD];
__device__ float g_V [(size_t)BATCH * S_LEN * KVHEADS * HD];
__device__ float g_AO[(size_t)BATCH * S_LEN * NHEADS  * HD];

// ---------------- wmma tf32 GEMM: C[M,N] = A[M,K] @ B[K,N], row-major ----------------
constexpr int WBM = 128, WBN = 128, WBK = 32;

__global__ __launch_bounds__(256)
void gemm_tf32(const float* __restrict__ A, const float* __restrict__ B,
               float* __restrict__ C, int K, int lda, int ldb, int ldc)
{
    const int bm = blockIdx.y, bn = blockIdx.x;

    __shared__ float As[WBM][WBK + 4];
    __shared__ float Bs[WBK][WBN + 4];

    const int tid = threadIdx.x;
    const int wid = tid >> 5;
    const int wm  = wid & 3;   // 4 warp-rows * 32 rows
    const int wn  = wid >> 2;  // 2 warp-cols * 64 cols

    wmma::fragment<wmma::accumulator, 16, 16, 8, float> acc[2][4];
    #pragma unroll
    for (int i = 0; i < 2; i++)
        #pragma unroll
        for (int j = 0; j < 4; j++)
            wmma::fill_fragment(acc[i][j], 0.0f);

    const int ktiles = K / WBK;

    for (int kt = 0; kt < ktiles; kt++) {
        #pragma unroll
        for (int f = tid; f < WBM * WBK / 4; f += 256) {
            int r = f >> 3, c = (f & 7) << 2;
            float4 v = *reinterpret_cast<const float4*>(
                A + (size_t)(bm * WBM + r) * lda + kt * WBK + c);
            As[r][c + 0] = v.x; As[r][c + 1] = v.y;
            As[r][c + 2] = v.z; As[r][c + 3] = v.w;
        }
        #pragma unroll
        for (int f = tid; f < WBK * WBN / 4; f += 256) {
            int r = f >> 5, c = (f & 31) << 2;
            float4 v = *reinterpret_cast<const float4*>(
                B + (size_t)(kt * WBK + r) * ldb + bn * WBN + c);
            Bs[r][c + 0] = v.x; Bs[r][c + 1] = v.y;
            Bs[r][c + 2] = v.z; Bs[r][c + 3] = v.w;
        }
        __syncthreads();

        #pragma unroll
        for (int kk = 0; kk < WBK; kk += 8) {
            wmma::fragment<wmma::matrix_a, 16, 16, 8, wmma::precision::tf32,
                           wmma::row_major> af[2];
            #pragma unroll
            for (int i = 0; i < 2; i++) {
                wmma::load_matrix_sync(af[i], &As[wm * 32 + i * 16][kk], WBK + 4);
                #pragma unroll
                for (int t = 0; t < af[i].num_elements; t++)
                    af[i].x[t] = wmma::__float_to_tf32(af[i].x[t]);
            }
            #pragma unroll
            for (int j = 0; j < 4; j++) {
                wmma::fragment<wmma::matrix_b, 16, 16, 8,
                               wmma::precision::tf32, wmma::row_major> bf;
                wmma::load_matrix_sync(bf, &Bs[kk][wn * 64 + j * 16], WBN + 4);
                #pragma unroll
                for (int t = 0; t < bf.num_elements; t++)
                    bf.x[t] = wmma::__float_to_tf32(bf.x[t]);
                #pragma unroll
                for (int i = 0; i < 2; i++)
                    wmma::mma_sync(acc[i][j], af[i], bf, acc[i][j]);
            }
        }
        __syncthreads();
    }

    #pragma unroll
    for (int i = 0; i < 2; i++)
        #pragma unroll
        for (int j = 0; j < 4; j++) {
            int row = bm * WBM + wm * 32 + i * 16;
            int col = bn * WBN + wn * 64 + j * 16;
            wmma::store_matrix_sync(C + (size_t)row * ldc + col,
                                    acc[i][j], ldc, wmma::mem_row_major);
        }
}

// ---------------- RoPE (in-place, fp32, fixed sincosf order) ----------------
__global__ void rope_kernel(float* buf, int nheads, long long total)
{
    long long idx = (long long)blockIdx.x * blockDim.x + threadIdx.x;
    if (idx >= total) return;
    int d = (int)(idx & 63);
    long long t = idx >> 6;
    int h = (int)(t % nheads);
    long long row = t / nheads;
    int s = (int)(row & (S_LEN - 1));

    float inv_freq = (float)exp2(-(double)d * (13.287712379549449 / 64.0));
    float ang = (float)s * inv_freq;
    float c, sn;
    sincosf(ang, &sn, &c);   // sincosf(x, &sin, &cos)

    float* p = buf + (row * nheads + h) * (long long)HD;
    float q1 = p[d];
    float q2 = p[d + 64];
    p[d]      = q1 * c - q2 * sn;
    p[d + 64] = q2 * c + q1 * sn;
}

// ---------------- fused causal flash attention (pre-rotated Q/K) ----------------
#define QROWPAD 132
#define PROWPAD 68

__global__ __launch_bounds__(256)
void flash_attn(const float* __restrict__ Q, const float* __restrict__ K,
                const float* __restrict__ V, float* __restrict__ O)
{
    extern __shared__ float sm[];
    float* Qs   = sm;
    float* KVs  = Qs + 64 * QROWPAD;
    float* Ps   = KVs + 64 * QROWPAD;
    float* Mrow = Ps + 64 * PROWPAD;
    float* Lrow = Mrow + 64;
    float* Srow = Lrow + 64;

    const int tid = threadIdx.x;
    const int tx = tid & 15, ty = tid >> 4;
    const int qr0 = blockIdx.x * 64;
    const int bh = blockIdx.y;
    const int b = bh >> 4, h = bh & 15;
    const int kvh = h >> 1;
    const float scale = 0.08838834764831845f;

    const float* Qbase = Q + ((size_t)(b * S_LEN + qr0) * NHEADS + h) * HD;
    #pragma unroll
    for (int i = 0; i < 8; i++) {
        int v = tid + i * 256;
        int r = v >> 5, c4 = (v & 31) << 2;
        *reinterpret_cast<float4*>(&Qs[r * QROWPAD + c4]) =
            *reinterpret_cast<const float4*>(Qbase + (size_t)r * (NHEADS * HD) + c4);
    }
    if (tid < 64) { Mrow[tid] = -INFINITY; Lrow[tid] = 0.0f; }

    float acc[4][8];
    #pragma unroll
    for (int i = 0; i < 4; i++)
        #pragma unroll
        for (int j = 0; j < 8; j++) acc[i][j] = 0.0f;

    const float* Kbase = K + ((size_t)b * S_LEN * KVHEADS + kvh) * HD;
    const float* Vbase = V + ((size_t)b * S_LEN * KVHEADS + kvh) * HD;

    for (int j0 = 0; j0 <= qr0; j0 += 64) {
        __syncthreads();
        #pragma unroll
        for (int i = 0; i < 8; i++) {
            int v = tid + i * 256;
            int r = v >> 5, c4 = (v & 31) << 2;
            *reinterpret_cast<float4*>(&KVs[r * QROWPAD + c4]) =
                *reinterpret_cast<const float4*>(Kbase + (size_t)(j0 + r) * (KVHEADS * HD) + c4);
        }
        __syncthreads();

        float s[4][4];
        #pragma unroll
        for (int i = 0; i < 4; i++)
            #pragma unroll
            for (int j = 0; j < 4; j++) s[i][j] = 0.0f;

        for (int d = 0; d < HD; d += 4) {
            float4 qa[4], kb[4];
            #pragma unroll
            for (int i = 0; i < 4; i++)
                qa[i] = *reinterpret_cast<const float4*>(&Qs[(ty * 4 + i) * QROWPAD + d]);
            #pragma unroll
            for (int j = 0; j < 4; j++)
                kb[j] = *reinterpret_cast<const float4*>(&KVs[(j * 16 + tx) * QROWPAD + d]);
            #pragma unroll
            for (int i = 0; i < 4; i++)
                #pragma unroll
                for (int j = 0; j < 4; j++)
                    s[i][j] += qa[i].x * kb[j].x + qa[i].y * kb[j].y
                             + qa[i].z * kb[j].z + qa[i].w * kb[j].w;
        }

        #pragma unroll
        for (int i = 0; i < 4; i++) {
            int rg = qr0 + ty * 4 + i;
            #pragma unroll
            for (int j = 0; j < 4; j++) {
                int cg = j0 + j * 16 + tx;
                float val = s[i][j] * scale;
                if (cg > rg) val = -INFINITY;
                Ps[(ty * 4 + i) * PROWPAD + j * 16 + tx] = val;
            }
        }
        __syncthreads();

        #pragma unroll
        for (int i = 0; i < 8; i++) {
            int v = tid + i * 256;
            int r = v >> 5, c4 = (v & 31) << 2;
            *reinterpret_cast<float4*>(&KVs[r * QROWPAD + c4]) =
                *reinterpret_cast<const float4*>(Vbase + (size_t)(j0 + r) * (KVHEADS * HD) + c4);
        }
        if (tid < 64) {
            float mold = Mrow[tid];
            float mt = mold;
            #pragma unroll 8
            for (int j = 0; j < 64; j++) mt = fmaxf(mt, Ps[tid * PROWPAD + j]);
            float factor = expf(mold - mt);
            float sum = 0.0f;
            #pragma unroll 8
            for (int j = 0; j < 64; j++) {
                float p = expf(Ps[tid * PROWPAD + j] - mt);
                Ps[tid * PROWPAD + j] = p;
                sum += p;
            }
            Mrow[tid] = mt;
            Lrow[tid] = Lrow[tid] * factor + sum;
            Srow[tid] = factor;
        }
        __syncthreads();

        #pragma unroll
        for (int i = 0; i < 4; i++) {
            float f = Srow[ty * 4 + i];
            #pragma unroll
            for (int j = 0; j < 8; j++) acc[i][j] *= f;
        }
        for (int j = 0; j < 64; j++) {
            float pr[4];
            #pragma unroll
            for (int i = 0; i < 4; i++) pr[i] = Ps[(ty * 4 + i) * PROWPAD + j];
            float4 v0 = *reinterpret_cast<const float4*>(&KVs[j * QROWPAD + tx * 8]);
            float4 v1 = *reinterpret_cast<const float4*>(&KVs[j * QROWPAD + tx * 8 + 4]);
            #pragma unroll
            for (int i = 0; i < 4; i++) {
                acc[i][0] += pr[i] * v0.x; acc[i][1] += pr[i] * v0.y;
                acc[i][2] += pr[i] * v0.z; acc[i][3] += pr[i] * v0.w;
                acc[i][4] += pr[i] * v1.x; acc[i][5] += pr[i] * v1.y;
                acc[i][6] += pr[i] * v1.z; acc[i][7] += pr[i] * v1.w;
            }
        }
    }

    float* Obase = O + ((size_t)(b * S_LEN + qr0) * NHEADS + h) * HD;
    #pragma unroll
    for (int i = 0; i < 4; i++) {
        int r = ty * 4 + i;
        float inv = 1.0f / Lrow[r];
        float4 o0, o1;
        o0.x = acc[i][0] * inv; o0.y = acc[i][1] * inv;
        o0.z = acc[i][2] * inv; o0.w = acc[i][3] * inv;
        o1.x = acc[i][4] * inv; o1.y = acc[i][5] * inv;
        o1.z = acc[i][6] * inv; o1.w = acc[i][7] * inv;
        *reinterpret_cast<float4*>(Obase + (size_t)r * (NHEADS * HD) + tx * 8)     = o0;
        *reinterpret_cast<float4*>(Obase + (size_t)r * (NHEADS * HD) + tx * 8 + 4) = o1;
    }
}

// ---------------- driver ----------------
extern "C" void kernel_launch(void* const* d_in, const int* in_sizes, int n_in,
                              void* d_out, int out_size)
{
    const float* x  = (const float*)d_in[0];
    const float* Wq = (const float*)d_in[1];
    const float* Wk = (const float*)d_in[2];
    const float* Wv = (const float*)d_in[3];
    const float* Wo = (const float*)d_in[4];
    float* out = (float*)d_out;

    float *Q, *K, *V, *AO;
    cudaGetSymbolAddress((void**)&Q,  g_Q);
    cudaGetSymbolAddress((void**)&K,  g_K);
    cudaGetSymbolAddress((void**)&V,  g_V);
    cudaGetSymbolAddress((void**)&AO, g_AO);

    const int M = BATCH * S_LEN;
    dim3 blk(256);

    // projections (wmma tf32)
    gemm_tf32<<<dim3((NHEADS * HD) / WBN, M / WBM), blk>>>(
        x, Wq, Q, DIM, DIM, NHEADS * HD, NHEADS * HD);
    gemm_tf32<<<dim3((KVHEADS * HD) / WBN, M / WBM), blk>>>(
        x, Wk, K, DIM, DIM, KVHEADS * HD, KVHEADS * HD);
    gemm_tf32<<<dim3((KVHEADS * HD) / WBN, M / WBM), blk>>>(
        x, Wv, V, DIM, DIM, KVHEADS * HD, KVHEADS * HD);

    // RoPE on Q and K (in place, fixed sincosf)
    {
        long long totQ = (long long)BATCH * S_LEN * NHEADS  * 64;
        long long totK = (long long)BATCH * S_LEN * KVHEADS * 64;
        rope_kernel<<<(unsigned)((totQ + 255) / 256), 256>>>(Q, NHEADS,  totQ);
        rope_kernel<<<(unsigned)((totK + 255) / 256), 256>>>(K, KVHEADS, totK);
    }

    // fused causal attention -> AO
    {
        const int smem = (64 * QROWPAD * 2 + 64 * PROWPAD + 192) * (int)sizeof(float);
        cudaFuncSetAttribute(flash_attn, cudaFuncAttributeMaxDynamicSharedMemorySize, smem);
        flash_attn<<<dim3(S_LEN / 64, BATCH * NHEADS), blk, smem>>>(Q, K, V, AO);
    }

    // out = AO @ Wo (wmma tf32)
    gemm_tf32<<<dim3(DIM / WBN, M / WBM), blk>>>(
        AO, Wo, out, NHEADS * HD, NHEADS * HD, DIM, DIM);
}

// round 14
// speedup vs baseline: 1.1931x; 1.1369x over previous
#include <cuda_runtime.h>
#include <mma.h>
#include <cstdint>

using namespace nvcuda;

#define BATCH   2
#define S_LEN   2048
#define DIM     2048
#define NHEADS  16
#define KVHEADS 8
#define HD      128

// ---------------- static scratch ----------------
__device__ float g_Q [(size_t)BATCH * S_LEN * NHEADS  * HD];
__device__ float g_K [(size_t)BATCH * S_LEN * KVHEADS * HD];
__device__ float g_V [(size_t)BATCH * S_LEN * KVHEADS * HD];
__device__ float g_AO[(size_t)BATCH * S_LEN * NHEADS  * HD];

// ---------------- wmma tf32 GEMM: C[M,N] = A[M,K] @ B[K,N], row-major ----------------
// tf32 rounding applied once during smem store; fragments used raw.
constexpr int WBM = 128, WBN = 128, WBK = 32;

__global__ __launch_bounds__(256)
void gemm_tf32(const float* __restrict__ A, const float* __restrict__ B,
               float* __restrict__ C, int K, int lda, int ldb, int ldc)
{
    const int bm = blockIdx.y, bn = blockIdx.x;

    __shared__ float As[WBM][WBK + 4];
    __shared__ float Bs[WBK][WBN + 4];

    const int tid = threadIdx.x;
    const int wid = tid >> 5;
    const int wm  = wid & 3;
    const int wn  = wid >> 2;

    wmma::fragment<wmma::accumulator, 16, 16, 8, float> acc[2][4];
    #pragma unroll
    for (int i = 0; i < 2; i++)
        #pragma unroll
        for (int j = 0; j < 4; j++)
            wmma::fill_fragment(acc[i][j], 0.0f);

    const int ktiles = K / WBK;

    for (int kt = 0; kt < ktiles; kt++) {
        #pragma unroll
        for (int f = tid; f < WBM * WBK / 4; f += 256) {
            int r = f >> 3, c = (f & 7) << 2;
            float4 v = *reinterpret_cast<const float4*>(
                A + (size_t)(bm * WBM + r) * lda + kt * WBK + c);
            As[r][c + 0] = wmma::__float_to_tf32(v.x);
            As[r][c + 1] = wmma::__float_to_tf32(v.y);
            As[r][c + 2] = wmma::__float_to_tf32(v.z);
            As[r][c + 3] = wmma::__float_to_tf32(v.w);
        }
        #pragma unroll
        for (int f = tid; f < WBK * WBN / 4; f += 256) {
            int r = f >> 5, c = (f & 31) << 2;
            float4 v = *reinterpret_cast<const float4*>(
                B + (size_t)(kt * WBK + r) * ldb + bn * WBN + c);
            Bs[r][c + 0] = wmma::__float_to_tf32(v.x);
            Bs[r][c + 1] = wmma::__float_to_tf32(v.y);
            Bs[r][c + 2] = wmma::__float_to_tf32(v.z);
            Bs[r][c + 3] = wmma::__float_to_tf32(v.w);
        }
        __syncthreads();

        #pragma unroll
        for (int kk = 0; kk < WBK; kk += 8) {
            wmma::fragment<wmma::matrix_a, 16, 16, 8, wmma::precision::tf32,
                           wmma::row_major> af[2];
            #pragma unroll
            for (int i = 0; i < 2; i++)
                wmma::load_matrix_sync(af[i], &As[wm * 32 + i * 16][kk], WBK + 4);
            #pragma unroll
            for (int j = 0; j < 4; j++) {
                wmma::fragment<wmma::matrix_b, 16, 16, 8,
                               wmma::precision::tf32, wmma::row_major> bf;
                wmma::load_matrix_sync(bf, &Bs[kk][wn * 64 + j * 16], WBN + 4);
                #pragma unroll
                for (int i = 0; i < 2; i++)
                    wmma::mma_sync(acc[i][j], af[i], bf, acc[i][j]);
            }
        }
        __syncthreads();
    }

    #pragma unroll
    for (int i = 0; i < 2; i++)
        #pragma unroll
        for (int j = 0; j < 4; j++) {
            int row = bm * WBM + wm * 32 + i * 16;
            int col = bn * WBN + wn * 64 + j * 16;
            wmma::store_matrix_sync(C + (size_t)row * ldc + col,
                                    acc[i][j], ldc, wmma::mem_row_major);
        }
}

// ---------------- RoPE (in-place, fp32, sincosf(x,&sin,&cos)) ----------------
__global__ void rope_kernel(float* buf, int nheads, long long total)
{
    long long idx = (long long)blockIdx.x * blockDim.x + threadIdx.x;
    if (idx >= total) return;
    int d = (int)(idx & 63);
    long long t = idx >> 6;
    int h = (int)(t % nheads);
    long long row = t / nheads;
    int s = (int)(row & (S_LEN - 1));

    float inv_freq = (float)exp2(-(double)d * (13.287712379549449 / 64.0));
    float ang = (float)s * inv_freq;
    float c, sn;
    sincosf(ang, &sn, &c);

    float* p = buf + (row * nheads + h) * (long long)HD;
    float q1 = p[d];
    float q2 = p[d + 64];
    p[d]      = q1 * c - q2 * sn;
    p[d + 64] = q2 * c + q1 * sn;
}

// ---------------- wmma tf32 fused causal flash attention ----------------
// grid (S/64, B*NHEADS), 256 threads (8 warps).
#define QROWPAD 132
#define PROWPAD 68

__global__ __launch_bounds__(256)
void flash_attn(const float* __restrict__ Q, const float* __restrict__ K,
                const float* __restrict__ V, float* __restrict__ O)
{
    extern __shared__ float sm[];
    float* Qs   = sm;                      // [64][132] tf32-rounded
    float* KVs  = Qs + 64 * QROWPAD;       // [64][132] K then V, tf32-rounded
    float* Os   = KVs + 64 * QROWPAD;      // [64][132] fp32 accumulated O
    float* Ps   = Os + 64 * QROWPAD;       // [64][68]
    float* Mrow = Ps + 64 * PROWPAD;       // [64]
    float* Lrow = Mrow + 64;               // [64]
    float* Srow = Lrow + 64;               // [64]

    const int tid = threadIdx.x;
    const int wid = tid >> 5;
    const int wm = wid & 3;                // 16-row strip
    const int wn = wid >> 2;               // 0/1
    const int qr0 = blockIdx.x * 64;
    const int bh = blockIdx.y;
    const int b = bh >> 4, h = bh & 15;
    const int kvh = h >> 1;
    const float scale = 0.08838834764831845f;

    // load Q tile (tf32-rounded), init Os/M/L
    const float* Qbase = Q + ((size_t)(b * S_LEN + qr0) * NHEADS + h) * HD;
    #pragma unroll
    for (int i = 0; i < 8; i++) {
        int v = tid + i * 256;
        int r = v >> 5, c4 = (v & 31) << 2;
        float4 q = *reinterpret_cast<const float4*>(Qbase + (size_t)r * (NHEADS * HD) + c4);
        Qs[r * QROWPAD + c4 + 0] = wmma::__float_to_tf32(q.x);
        Qs[r * QROWPAD + c4 + 1] = wmma::__float_to_tf32(q.y);
        Qs[r * QROWPAD + c4 + 2] = wmma::__float_to_tf32(q.z);
        Qs[r * QROWPAD + c4 + 3] = wmma::__float_to_tf32(q.w);
        Os[r * QROWPAD + c4 + 0] = 0.0f;
        Os[r * QROWPAD + c4 + 1] = 0.0f;
        Os[r * QROWPAD + c4 + 2] = 0.0f;
        Os[r * QROWPAD + c4 + 3] = 0.0f;
    }
    if (tid < 64) { Mrow[tid] = -INFINITY; Lrow[tid] = 0.0f; }

    const float* Kbase = K + ((size_t)b * S_LEN * KVHEADS + kvh) * HD;
    const float* Vbase = V + ((size_t)b * S_LEN * KVHEADS + kvh) * HD;

    for (int j0 = 0; j0 <= qr0; j0 += 64) {
        __syncthreads();   // Qs/Os init visible (iter 0); prev PV done (KVs free)

        // load K tile (tf32-rounded)
        #pragma unroll
        for (int i = 0; i < 8; i++) {
            int v = tid + i * 256;
            int r = v >> 5, c4 = (v & 31) << 2;
            float4 kv = *reinterpret_cast<const float4*>(
                Kbase + (size_t)(j0 + r) * (KVHEADS * HD) + c4);
            KVs[r * QROWPAD + c4 + 0] = wmma::__float_to_tf32(kv.x);
            KVs[r * QROWPAD + c4 + 1] = wmma::__float_to_tf32(kv.y);
            KVs[r * QROWPAD + c4 + 2] = wmma::__float_to_tf32(kv.z);
            KVs[r * QROWPAD + c4 + 3] = wmma::__float_to_tf32(kv.w);
        }
        __syncthreads();

        // ---- scores: S[64,64] = Qs @ KVs^T  (warp: 16 rows x 32 cols) ----
        {
            wmma::fragment<wmma::accumulator, 16, 16, 8, float> sacc[2];
            wmma::fill_fragment(sacc[0], 0.0f);
            wmma::fill_fragment(sacc[1], 0.0f);
            #pragma unroll
            for (int kk = 0; kk < HD; kk += 8) {
                wmma::fragment<wmma::matrix_a, 16, 16, 8, wmma::precision::tf32,
                               wmma::row_major> af;
                wmma::load_matrix_sync(af, &Qs[(wm * 16) * QROWPAD + kk], QROWPAD);
                #pragma unroll
                for (int j = 0; j < 2; j++) {
                    wmma::fragment<wmma::matrix_b, 16, 16, 8, wmma::precision::tf32,
                                   wmma::col_major> bf;
                    wmma::load_matrix_sync(bf, &KVs[(wn * 32 + j * 16) * QROWPAD + kk], QROWPAD);
                    wmma::mma_sync(sacc[j], af, bf, sacc[j]);
                }
            }
            #pragma unroll
            for (int j = 0; j < 2; j++)
                wmma::store_matrix_sync(&Ps[(wm * 16) * PROWPAD + wn * 32 + j * 16],
                                        sacc[j], PROWPAD, wmma::mem_row_major);
        }
        __syncthreads();   // Ps visible

        // load V tile into KVs (tf32-rounded) — scores no longer need K
        #pragma unroll
        for (int i = 0; i < 8; i++) {
            int v = tid + i * 256;
            int r = v >> 5, c4 = (v & 31) << 2;
            float4 kv = *reinterpret_cast<const float4*>(
                Vbase + (size_t)(j0 + r) * (KVHEADS * HD) + c4);
            KVs[r * QROWPAD + c4 + 0] = wmma::__float_to_tf32(kv.x);
            KVs[r * QROWPAD + c4 + 1] = wmma::__float_to_tf32(kv.y);
            KVs[r * QROWPAD + c4 + 2] = wmma::__float_to_tf32(kv.z);
            KVs[r * QROWPAD + c4 + 3] = wmma::__float_to_tf32(kv.w);
        }

        // ---- online softmax: 4 threads per row ----
        {
            const int row = tid >> 2;          // 0..63
            const int sub = tid & 3;           // 16 cols each
            const int rg = qr0 + row;
            float vals[16];
            float mpart = -INFINITY;
            #pragma unroll
            for (int jj = 0; jj < 16; jj++) {
                int cg = j0 + sub * 16 + jj;
                float vv = Ps[row * PROWPAD + sub * 16 + jj] * scale;
                vals[jj] = (cg > rg) ? -INFINITY : vv;
                mpart = fmaxf(mpart, vals[jj]);
            }
            mpart = fmaxf(mpart, __shfl_xor_sync(0xffffffffu, mpart, 1));
            mpart = fmaxf(mpart, __shfl_xor_sync(0xffffffffu, mpart, 2));
            float mold = Mrow[row];
            float mt = fmaxf(mold, mpart);
            float spart = 0.0f;
            #pragma unroll
            for (int jj = 0; jj < 16; jj++) {
                float p = (vals[jj] == -INFINITY) ? 0.0f : expf(vals[jj] - mt);
                Ps[row * PROWPAD + sub * 16 + jj] = wmma::__float_to_tf32(p);
                spart += p;
            }
            spart += __shfl_xor_sync(0xffffffffu, spart, 1);
            spart += __shfl_xor_sync(0xffffffffu, spart, 2);
            if (sub == 0) {
                float factor = expf(mold - mt);   // 0 when mold == -inf
                Mrow[row] = mt;
                Lrow[row] = Lrow[row] * factor + spart;
                Srow[row] = factor;
            }
        }
        __syncthreads();   // Ps(probs), Srow, V tile visible

        // ---- rescale Os rows by factor ----
        #pragma unroll
        for (int i = 0; i < 8; i++) {
            int v = tid + i * 256;
            int r = v >> 5, c4 = (v & 31) << 2;
            float f = Srow[r];
            float4 o = *reinterpret_cast<float4*>(&Os[r * QROWPAD + c4]);
            o.x *= f; o.y *= f; o.z *= f; o.w *= f;
            *reinterpret_cast<float4*>(&Os[r * QROWPAD + c4]) = o;
        }
        __syncthreads();   // rescale done

        // ---- PV: Os[64,128] += Ps[64,64] @ KVs[64,128]  (warp: 16 rows x 64 cols) ----
        {
            wmma::fragment<wmma::accumulator, 16, 16, 8, float> oacc[4];
            #pragma unroll
            for (int j = 0; j < 4; j++)
                wmma::load_matrix_sync(oacc[j],
                    &Os[(wm * 16) * QROWPAD + wn * 64 + j * 16], QROWPAD,
                    wmma::mem_row_major);
            #pragma unroll
            for (int kk = 0; kk < 64; kk += 8) {
                wmma::fragment<wmma::matrix_a, 16, 16, 8, wmma::precision::tf32,
                               wmma::row_major> af;
                wmma::load_matrix_sync(af, &Ps[(wm * 16) * PROWPAD + kk], PROWPAD);
                #pragma unroll
                for (int j = 0; j < 4; j++) {
                    wmma::fragment<wmma::matrix_b, 16, 16, 8, wmma::precision::tf32,
                                   wmma::row_major> bf;
                    wmma::load_matrix_sync(bf, &KVs[kk * QROWPAD + wn * 64 + j * 16], QROWPAD);
                    wmma::mma_sync(oacc[j], af, bf, oacc[j]);
                }
            }
            #pragma unroll
            for (int j = 0; j < 4; j++)
                wmma::store_matrix_sync(&Os[(wm * 16) * QROWPAD + wn * 64 + j * 16],
                                        oacc[j], QROWPAD, wmma::mem_row_major);
        }
    }
    __syncthreads();

    // epilogue: O = Os / Lrow
    float* Obase = O + ((size_t)(b * S_LEN + qr0) * NHEADS + h) * HD;
    #pragma unroll
    for (int i = 0; i < 8; i++) {
        int v = tid + i * 256;
        int r = v >> 5, c4 = (v & 31) << 2;
        float inv = 1.0f / Lrow[r];
        float4 o = *reinterpret_cast<float4*>(&Os[r * QROWPAD + c4]);
        o.x *= inv; o.y *= inv; o.z *= inv; o.w *= inv;
        *reinterpret_cast<float4*>(Obase + (size_t)r * (NHEADS * HD) + c4) = o;
    }
}

// ---------------- driver ----------------
extern "C" void kernel_launch(void* const* d_in, const int* in_sizes, int n_in,
                              void* d_out, int out_size)
{
    const float* x  = (const float*)d_in[0];
    const float* Wq = (const float*)d_in[1];
    const float* Wk = (const float*)d_in[2];
    const float* Wv = (const float*)d_in[3];
    const float* Wo = (const float*)d_in[4];
    float* out = (float*)d_out;

    float *Q, *K, *V, *AO;
    cudaGetSymbolAddress((void**)&Q,  g_Q);
    cudaGetSymbolAddress((void**)&K,  g_K);
    cudaGetSymbolAddress((void**)&V,  g_V);
    cudaGetSymbolAddress((void**)&AO, g_AO);

    const int M = BATCH * S_LEN;
    dim3 blk(256);

    gemm_tf32<<<dim3((NHEADS * HD) / WBN, M / WBM), blk>>>(
        x, Wq, Q, DIM, DIM, NHEADS * HD, NHEADS * HD);
    gemm_tf32<<<dim3((KVHEADS * HD) / WBN, M / WBM), blk>>>(
        x, Wk, K, DIM, DIM, KVHEADS * HD, KVHEADS * HD);
    gemm_tf32<<<dim3((KVHEADS * HD) / WBN, M / WBM), blk>>>(
        x, Wv, V, DIM, DIM, KVHEADS * HD, KVHEADS * HD);

    {
        long long totQ = (long long)BATCH * S_LEN * NHEADS  * 64;
        long long totK = (long long)BATCH * S_LEN * KVHEADS * 64;
        rope_kernel<<<(unsigned)((totQ + 255) / 256), 256>>>(Q, NHEADS,  totQ);
        rope_kernel<<<(unsigned)((totK + 255) / 256), 256>>>(K, KVHEADS, totK);
    }

    {
        const int smem = (64 * QROWPAD * 3 + 64 * PROWPAD + 192) * (int)sizeof(float);
        cudaFuncSetAttribute(flash_attn, cudaFuncAttributeMaxDynamicSharedMemorySize, smem);
        flash_attn<<<dim3(S_LEN / 64, BATCH * NHEADS), blk, smem>>>(Q, K, V, AO);
    }

    gemm_tf32<<<dim3(DIM / WBN, M / WBM), blk>>>(
        AO, Wo, out, NHEADS * HD, NHEADS * HD, DIM, DIM);
}

// round 15
// speedup vs baseline: 1.3459x; 1.1281x over previous
#include <cuda_runtime.h>
#include <mma.h>
#include <cstdint>

using namespace nvcuda;

#define BATCH   2
#define S_LEN   2048
#define DIM     2048
#define NHEADS  16
#define KVHEADS 8
#define HD      128

// ---------------- static scratch ----------------
__device__ float g_Q [(size_t)BATCH * S_LEN * NHEADS  * HD];
__device__ float g_K [(size_t)BATCH * S_LEN * KVHEADS * HD];
__device__ float g_V [(size_t)BATCH * S_LEN * KVHEADS * HD];
__device__ float g_AO[(size_t)BATCH * S_LEN * NHEADS  * HD];

// ---------------- cp.async helpers ----------------
__device__ __forceinline__ void cp_async16(void* smem_dst, const void* gmem_src) {
    uint32_t s = (uint32_t)__cvta_generic_to_shared(smem_dst);
    asm volatile("cp.async.cg.shared.global [%0], [%1], 16;\n" :: "r"(s), "l"(gmem_src));
}
__device__ __forceinline__ void cp_commit() {
    asm volatile("cp.async.commit_group;\n");
}
template <int N>
__device__ __forceinline__ void cp_wait() {
    asm volatile("cp.async.wait_group %0;\n" :: "n"(N));
}

// ---------------- double-buffered cp.async wmma tf32 GEMM ----------------
// C[M,N] = A[M,K] @ B[K,N], row-major. tf32 RN rounding done in-fragment.
constexpr int WBM = 128, WBN = 128, WBK = 32;
constexpr int A_LD = WBK + 4;    // 36 floats (144B, 16B-mult)
constexpr int B_LD = WBN + 4;    // 132 floats (528B, 16B-mult)
constexpr int A_SZ = WBM * A_LD; // 4608 floats
constexpr int B_SZ = WBK * B_LD; // 4224 floats
constexpr int GEMM_SMEM_BYTES = 2 * (A_SZ + B_SZ) * 4;  // 70656 B

__global__ __launch_bounds__(256)
void gemm_tf32(const float* __restrict__ A, const float* __restrict__ B,
               float* __restrict__ C, int K, int lda, int ldb, int ldc)
{
    extern __shared__ float smem[];
    float* Abuf[2] = { smem,              smem + A_SZ + B_SZ };
    float* Bbuf[2] = { smem + A_SZ,       smem + 2 * A_SZ + B_SZ };

    const int bm = blockIdx.y, bn = blockIdx.x;
    const int tid = threadIdx.x;
    const int wid = tid >> 5;
    const int wm  = wid & 3;
    const int wn  = wid >> 2;

    wmma::fragment<wmma::accumulator, 16, 16, 8, float> acc[2][4];
    #pragma unroll
    for (int i = 0; i < 2; i++)
        #pragma unroll
        for (int j = 0; j < 4; j++)
            wmma::fill_fragment(acc[i][j], 0.0f);

    const int ktiles = K / WBK;

    // prefetch indices (4 x 16B per thread for each of A and B)
    const int ar = tid >> 1;               // A: rows 0..127, two 16B chunks/row? no:
    // A tile 128x32 floats = 1024 16B-chunks: f = tid + i*256, r=f>>3, c=(f&7)*4
    // B tile 32x128 floats = 1024 16B-chunks: f = tid + i*256, r=f>>5, c=(f&31)*4
    (void)ar;

    auto loadA = [&](float* As, int kt) {
        #pragma unroll
        for (int i = 0; i < 4; i++) {
            int f = tid + i * 256;
            int r = f >> 3, c4 = (f & 7) << 2;
            cp_async16(As + r * A_LD + c4,
                       A + (size_t)(bm * WBM + r) * lda + kt * WBK + c4);
        }
    };
    auto loadB = [&](float* Bs, int kt) {
        #pragma unroll
        for (int i = 0; i < 4; i++) {
            int f = tid + i * 256;
            int r = f >> 5, c4 = (f & 31) << 2;
            cp_async16(Bs + r * B_LD + c4,
                       B + (size_t)(kt * WBK + r) * ldb + bn * WBN + c4);
        }
    };

    loadA(Abuf[0], 0); loadB(Bbuf[0], 0); cp_commit();

    for (int kt = 0; kt < ktiles; kt++) {
        if (kt + 1 < ktiles) {
            loadA(Abuf[(kt + 1) & 1], kt + 1);
            loadB(Bbuf[(kt + 1) & 1], kt + 1);
            cp_commit();
            cp_wait<1>();   // current tile's group done
        } else {
            cp_wait<0>();
        }
        __syncthreads();

        const float* As = Abuf[kt & 1];
        const float* Bs = Bbuf[kt & 1];

        #pragma unroll
        for (int kk = 0; kk < WBK; kk += 8) {
            wmma::fragment<wmma::matrix_a, 16, 16, 8, wmma::precision::tf32,
                           wmma::row_major> af[2];
            #pragma unroll
            for (int i = 0; i < 2; i++) {
                wmma::load_matrix_sync(af[i], As + (wm * 32 + i * 16) * A_LD + kk, A_LD);
                #pragma unroll
                for (int t = 0; t < af[i].num_elements; t++)
                    af[i].x[t] = wmma::__float_to_tf32(af[i].x[t]);
            }
            #pragma unroll
            for (int j = 0; j < 4; j++) {
                wmma::fragment<wmma::matrix_b, 16, 16, 8,
                               wmma::precision::tf32, wmma::row_major> bf;
                wmma::load_matrix_sync(bf, Bs + kk * B_LD + wn * 64 + j * 16, B_LD);
                #pragma unroll
                for (int t = 0; t < bf.num_elements; t++)
                    bf.x[t] = wmma::__float_to_tf32(bf.x[t]);
                #pragma unroll
                for (int i = 0; i < 2; i++)
                    wmma::mma_sync(acc[i][j], af[i], bf, acc[i][j]);
            }
        }
        __syncthreads();
    }

    #pragma unroll
    for (int i = 0; i < 2; i++)
        #pragma unroll
        for (int j = 0; j < 4; j++) {
            int row = bm * WBM + wm * 32 + i * 16;
            int col = bn * WBN + wn * 64 + j * 16;
            wmma::store_matrix_sync(C + (size_t)row * ldc + col,
                                    acc[i][j], ldc, wmma::mem_row_major);
        }
}

// ---------------- RoPE (in-place, fp32, sincosf(x,&sin,&cos)) ----------------
__global__ void rope_kernel(float* buf, int nheads, long long total)
{
    long long idx = (long long)blockIdx.x * blockDim.x + threadIdx.x;
    if (idx >= total) return;
    int d = (int)(idx & 63);
    long long t = idx >> 6;
    int h = (int)(t % nheads);
    long long row = t / nheads;
    int s = (int)(row & (S_LEN - 1));

    float inv_freq = (float)exp2(-(double)d * (13.287712379549449 / 64.0));
    float ang = (float)s * inv_freq;
    float c, sn;
    sincosf(ang, &sn, &c);

    float* p = buf + (row * nheads + h) * (long long)HD;
    float q1 = p[d];
    float q2 = p[d + 64];
    p[d]      = q1 * c - q2 * sn;
    p[d + 64] = q2 * c + q1 * sn;
}

// ---------------- wmma tf32 fused causal flash attention ----------------
#define QROWPAD 132
#define PROWPAD 68

__global__ __launch_bounds__(256)
void flash_attn(const float* __restrict__ Q, const float* __restrict__ K,
                const float* __restrict__ V, float* __restrict__ O)
{
    extern __shared__ float sm[];
    float* Qs   = sm;                      // [64][132] tf32-rounded
    float* KVs  = Qs + 64 * QROWPAD;       // [64][132] K then V, tf32-rounded
    float* Os   = KVs + 64 * QROWPAD;      // [64][132] fp32 accumulated O
    float* Ps   = Os + 64 * QROWPAD;       // [64][68]
    float* Mrow = Ps + 64 * PROWPAD;       // [64]
    float* Lrow = Mrow + 64;               // [64]
    float* Srow = Lrow + 64;               // [64]

    const int tid = threadIdx.x;
    const int wid = tid >> 5;
    const int wm = wid & 3;
    const int wn = wid >> 2;
    const int qr0 = blockIdx.x * 64;
    const int bh = blockIdx.y;
    const int b = bh >> 4, h = bh & 15;
    const int kvh = h >> 1;
    const float scale = 0.08838834764831845f;

    const float* Qbase = Q + ((size_t)(b * S_LEN + qr0) * NHEADS + h) * HD;
    #pragma unroll
    for (int i = 0; i < 8; i++) {
        int v = tid + i * 256;
        int r = v >> 5, c4 = (v & 31) << 2;
        float4 q = *reinterpret_cast<const float4*>(Qbase + (size_t)r * (NHEADS * HD) + c4);
        Qs[r * QROWPAD + c4 + 0] = wmma::__float_to_tf32(q.x);
        Qs[r * QROWPAD + c4 + 1] = wmma::__float_to_tf32(q.y);
        Qs[r * QROWPAD + c4 + 2] = wmma::__float_to_tf32(q.z);
        Qs[r * QROWPAD + c4 + 3] = wmma::__float_to_tf32(q.w);
        Os[r * QROWPAD + c4 + 0] = 0.0f;
        Os[r * QROWPAD + c4 + 1] = 0.0f;
        Os[r * QROWPAD + c4 + 2] = 0.0f;
        Os[r * QROWPAD + c4 + 3] = 0.0f;
    }
    if (tid < 64) { Mrow[tid] = -INFINITY; Lrow[tid] = 0.0f; }

    const float* Kbase = K + ((size_t)b * S_LEN * KVHEADS + kvh) * HD;
    const float* Vbase = V + ((size_t)b * S_LEN * KVHEADS + kvh) * HD;

    for (int j0 = 0; j0 <= qr0; j0 += 64) {
        __syncthreads();

        #pragma unroll
        for (int i = 0; i < 8; i++) {
            int v = tid + i * 256;
            int r = v >> 5, c4 = (v & 31) << 2;
            float4 kv = *reinterpret_cast<const float4*>(
                Kbase + (size_t)(j0 + r) * (KVHEADS * HD) + c4);
            KVs[r * QROWPAD + c4 + 0] = wmma::__float_to_tf32(kv.x);
            KVs[r * QROWPAD + c4 + 1] = wmma::__float_to_tf32(kv.y);
            KVs[r * QROWPAD + c4 + 2] = wmma::__float_to_tf32(kv.z);
            KVs[r * QROWPAD + c4 + 3] = wmma::__float_to_tf32(kv.w);
        }
        __syncthreads();

        // scores: S[64,64] = Qs @ KVs^T
        {
            wmma::fragment<wmma::accumulator, 16, 16, 8, float> sacc[2];
            wmma::fill_fragment(sacc[0], 0.0f);
            wmma::fill_fragment(sacc[1], 0.0f);
            #pragma unroll
            for (int kk = 0; kk < HD; kk += 8) {
                wmma::fragment<wmma::matrix_a, 16, 16, 8, wmma::precision::tf32,
                               wmma::row_major> af;
                wmma::load_matrix_sync(af, &Qs[(wm * 16) * QROWPAD + kk], QROWPAD);
                #pragma unroll
                for (int j = 0; j < 2; j++) {
                    wmma::fragment<wmma::matrix_b, 16, 16, 8, wmma::precision::tf32,
                                   wmma::col_major> bf;
                    wmma::load_matrix_sync(bf, &KVs[(wn * 32 + j * 16) * QROWPAD + kk], QROWPAD);
                    wmma::mma_sync(sacc[j], af, bf, sacc[j]);
                }
            }
            #pragma unroll
            for (int j = 0; j < 2; j++)
                wmma::store_matrix_sync(&Ps[(wm * 16) * PROWPAD + wn * 32 + j * 16],
                                        sacc[j], PROWPAD, wmma::mem_row_major);
        }
        __syncthreads();

        // load V tile into KVs
        #pragma unroll
        for (int i = 0; i < 8; i++) {
            int v = tid + i * 256;
            int r = v >> 5, c4 = (v & 31) << 2;
            float4 kv = *reinterpret_cast<const float4*>(
                Vbase + (size_t)(j0 + r) * (KVHEADS * HD) + c4);
            KVs[r * QROWPAD + c4 + 0] = wmma::__float_to_tf32(kv.x);
            KVs[r * QROWPAD + c4 + 1] = wmma::__float_to_tf32(kv.y);
            KVs[r * QROWPAD + c4 + 2] = wmma::__float_to_tf32(kv.z);
            KVs[r * QROWPAD + c4 + 3] = wmma::__float_to_tf32(kv.w);
        }

        // online softmax: 4 threads per row
        {
            const int row = tid >> 2;
            const int sub = tid & 3;
            const int rg = qr0 + row;
            float vals[16];
            float mpart = -INFINITY;
            #pragma unroll
            for (int jj = 0; jj < 16; jj++) {
                int cg = j0 + sub * 16 + jj;
                float vv = Ps[row * PROWPAD + sub * 16 + jj] * scale;
                vals[jj] = (cg > rg) ? -INFINITY : vv;
                mpart = fmaxf(mpart, vals[jj]);
            }
            mpart = fmaxf(mpart, __shfl_xor_sync(0xffffffffu, mpart, 1));
            mpart = fmaxf(mpart, __shfl_xor_sync(0xffffffffu, mpart, 2));
            float mold = Mrow[row];
            float mt = fmaxf(mold, mpart);
            float spart = 0.0f;
            #pragma unroll
            for (int jj = 0; jj < 16; jj++) {
                float p = (vals[jj] == -INFINITY) ? 0.0f : expf(vals[jj] - mt);
                Ps[row * PROWPAD + sub * 16 + jj] = wmma::__float_to_tf32(p);
                spart += p;
            }
            spart += __shfl_xor_sync(0xffffffffu, spart, 1);
            spart += __shfl_xor_sync(0xffffffffu, spart, 2);
            if (sub == 0) {
                float factor = expf(mold - mt);
                Mrow[row] = mt;
                Lrow[row] = Lrow[row] * factor + spart;
                Srow[row] = factor;
            }
        }
        __syncthreads();

        // rescale Os rows (skip rows whose factor is exactly 1)
        #pragma unroll
        for (int i = 0; i < 8; i++) {
            int v = tid + i * 256;
            int r = v >> 5, c4 = (v & 31) << 2;
            float f = Srow[r];
            if (f != 1.0f) {
                float4 o = *reinterpret_cast<float4*>(&Os[r * QROWPAD + c4]);
                o.x *= f; o.y *= f; o.z *= f; o.w *= f;
                *reinterpret_cast<float4*>(&Os[r * QROWPAD + c4]) = o;
            }
        }
        __syncthreads();

        // PV: Os += Ps @ KVs
        {
            wmma::fragment<wmma::accumulator, 16, 16, 8, float> oacc[4];
            #pragma unroll
            for (int j = 0; j < 4; j++)
                wmma::load_matrix_sync(oacc[j],
                    &Os[(wm * 16) * QROWPAD + wn * 64 + j * 16], QROWPAD,
                    wmma::mem_row_major);
            #pragma unroll
            for (int kk = 0; kk < 64; kk += 8) {
                wmma::fragment<wmma::matrix_a, 16, 16, 8, wmma::precision::tf32,
                               wmma::row_major> af;
                wmma::load_matrix_sync(af, &Ps[(wm * 16) * PROWPAD + kk], PROWPAD);
                #pragma unroll
                for (int j = 0; j < 4; j++) {
                    wmma::fragment<wmma::matrix_b, 16, 16, 8, wmma::precision::tf32,
                                   wmma::row_major> bf;
                    wmma::load_matrix_sync(bf, &KVs[kk * QROWPAD + wn * 64 + j * 16], QROWPAD);
                    wmma::mma_sync(oacc[j], af, bf, oacc[j]);
                }
            }
            #pragma unroll
            for (int j = 0; j < 4; j++)
                wmma::store_matrix_sync(&Os[(wm * 16) * QROWPAD + wn * 64 + j * 16],
                                        oacc[j], QROWPAD, wmma::mem_row_major);
        }
    }
    __syncthreads();

    float* Obase = O + ((size_t)(b * S_LEN + qr0) * NHEADS + h) * HD;
    #pragma unroll
    for (int i = 0; i < 8; i++) {
        int v = tid + i * 256;
        int r = v >> 5, c4 = (v & 31) << 2;
        float inv = 1.0f / Lrow[r];
        float4 o = *reinterpret_cast<float4*>(&Os[r * QROWPAD + c4]);
        o.x *= inv; o.y *= inv; o.z *= inv; o.w *= inv;
        *reinterpret_cast<float4*>(Obase + (size_t)r * (NHEADS * HD) + c4) = o;
    }
}

// ---------------- driver ----------------
extern "C" void kernel_launch(void* const* d_in, const int* in_sizes, int n_in,
                              void* d_out, int out_size)
{
    const float* x  = (const float*)d_in[0];
    const float* Wq = (const float*)d_in[1];
    const float* Wk = (const float*)d_in[2];
    const float* Wv = (const float*)d_in[3];
    const float* Wo = (const float*)d_in[4];
    float* out = (float*)d_out;

    float *Q, *K, *V, *AO;
    cudaGetSymbolAddress((void**)&Q,  g_Q);
    cudaGetSymbolAddress((void**)&K,  g_K);
    cudaGetSymbolAddress((void**)&V,  g_V);
    cudaGetSymbolAddress((void**)&AO, g_AO);

    const int M = BATCH * S_LEN;
    dim3 blk(256);

    cudaFuncSetAttribute(gemm_tf32, cudaFuncAttributeMaxDynamicSharedMemorySize,
                         GEMM_SMEM_BYTES);

    gemm_tf32<<<dim3((NHEADS * HD) / WBN, M / WBM), blk, GEMM_SMEM_BYTES>>>(
        x, Wq, Q, DIM, DIM, NHEADS * HD, NHEADS * HD);
    gemm_tf32<<<dim3((KVHEADS * HD) / WBN, M / WBM), blk, GEMM_SMEM_BYTES>>>(
        x, Wk, K, DIM, DIM, KVHEADS * HD, KVHEADS * HD);
    gemm_tf32<<<dim3((KVHEADS * HD) / WBN, M / WBM), blk, GEMM_SMEM_BYTES>>>(
        x, Wv, V, DIM, DIM, KVHEADS * HD, KVHEADS * HD);

    {
        long long totQ = (long long)BATCH * S_LEN * NHEADS  * 64;
        long long totK = (long long)BATCH * S_LEN * KVHEADS * 64;
        rope_kernel<<<(unsigned)((totQ + 255) / 256), 256>>>(Q, NHEADS,  totQ);
        rope_kernel<<<(unsigned)((totK + 255) / 256), 256>>>(K, KVHEADS, totK);
    }

    {
        const int smem = (64 * QROWPAD * 3 + 64 * PROWPAD + 192) * (int)sizeof(float);
        cudaFuncSetAttribute(flash_attn, cudaFuncAttributeMaxDynamicSharedMemorySize, smem);
        flash_attn<<<dim3(S_LEN / 64, BATCH * NHEADS), blk, smem>>>(Q, K, V, AO);
    }

    gemm_tf32<<<dim3(DIM / WBN, M / WBM), blk, GEMM_SMEM_BYTES>>>(
        AO, Wo, out, NHEADS * HD, NHEADS * HD, DIM, DIM);
}